// round 3
// baseline (speedup 1.0000x reference)
#include <cuda_runtime.h>
#include <cstdint>

// ---------------------------------------------------------------------------
// Problem constants (compile-time, derived from reference _compute_offsets()):
//   Level l: scale = 16*2^l - 1, resolution = 16*2^l, verts/axis r1 = 16*2^l+1
//   Dense levels: 0 (r1=17, size 4920), 1 (r1=33, size 35944), 2 (r1=65, size 274632)
//   Hashed levels 3..15: size 524288 each (2^19 -> mask 0x7FFFF)
//   Offsets: 0, 4920, 40864, 315496 + (l-3)*524288 ; TOTAL = 7131240
// ---------------------------------------------------------------------------

#define TOTAL_PARAMS 7131240
#define HASH_MASK    0x7FFFFu
#define PRIME_Y      2654435761u
#define PRIME_Z      805459861u

__device__ __align__(16) float2 g_sums[TOTAL_PARAMS];
__device__ __align__(16) int    g_counts[TOTAL_PARAMS];

__global__ void __launch_bounds__(256) zero_kernel() {
    float4* s = reinterpret_cast<float4*>(g_sums);
    int4*   c = reinterpret_cast<int4*>(g_counts);
    const size_t ns = (size_t)TOTAL_PARAMS * 2 / 4;
    const size_t nc = (size_t)TOTAL_PARAMS / 4;
    const size_t stride = (size_t)gridDim.x * blockDim.x;
    size_t t = (size_t)blockIdx.x * blockDim.x + threadIdx.x;
    for (size_t i = t; i < ns; i += stride) s[i] = make_float4(0.f, 0.f, 0.f, 0.f);
    for (size_t i = t; i < nc; i += stride) c[i] = make_int4(0, 0, 0, 0);
}

__global__ void __launch_bounds__(256) scatter_kernel(
    const float2* __restrict__ emb, const int* __restrict__ sidx, int n) {
    int i = blockIdx.x * blockDim.x + threadIdx.x;
    if (i >= n) return;
    int idx = sidx[i];
    float2 e = emb[i];
    atomicAdd(&g_sums[idx], e);
    atomicAdd(&g_counts[idx], 1);
}

__global__ void __launch_bounds__(256) finalize_kernel(
    const float2* __restrict__ fs, int n) {
    int i = blockIdx.x * blockDim.x + threadIdx.x;
    if (i >= n) return;
    int c = g_counts[i];
    float2 v;
    if (c > 0) {
        float2 s = g_sums[i];
        float inv = 1.0f / (float)c;
        v.x = s.x * inv;
        v.y = s.y * inv;
    } else {
        v = fs[i];
    }
    g_sums[i] = v;
}

__global__ void __launch_bounds__(256) encode_kernel(
    const float* __restrict__ inp,
    const int*   __restrict__ bound_ptr,
    float*       __restrict__ out,
    int B) {
    int b = blockIdx.x * blockDim.x + threadIdx.x;
    if (b >= B) return;

    float bound = 1.0f;
    if (bound_ptr) {
        int raw = bound_ptr[0];
        bound = (raw > 0 && raw < 1000000) ? (float)raw : __int_as_float(raw);
    }
    const float half_inv = 0.5f / bound;

    float x0 = (inp[3 * b + 0] + bound) * half_inv;
    float x1 = (inp[3 * b + 1] + bound) * half_inv;
    float x2 = (inp[3 * b + 2] + bound) * half_inv;

    const float2* __restrict__ table = (const float2*)g_sums;

    float r[32];

#pragma unroll
    for (int l = 0; l < 16; ++l) {
        const float scale = (float)((16 << l) - 1);
        float p0 = x0 * scale + 0.5f;
        float p1 = x1 * scale + 0.5f;
        float p2 = x2 * scale + 0.5f;
        float g0 = floorf(p0), g1 = floorf(p1), g2 = floorf(p2);
        float f0 = p0 - g0, f1 = p1 - g1, f2 = p2 - g2;
        int   i0 = (int)g0, i1 = (int)g1, i2 = (int)g2;

        int off;
        unsigned idx[8];
        if (l < 3) {
            const int r1  = (l == 0) ? 17 : (l == 1) ? 33 : 65;
            off           = (l == 0) ? 0  : (l == 1) ? 4920 : 40864;
            const int r1s = r1 * r1;
            int base = i0 + i1 * r1 + i2 * r1s;
#pragma unroll
            for (int c = 0; c < 8; ++c)
                idx[c] = (unsigned)(base + (c & 1) + ((c >> 1) & 1) * r1 +
                                    ((c >> 2) & 1) * r1s);
        } else {
            off = 315496 + (l - 3) * 524288;
            unsigned hx0 = (unsigned)i0;
            unsigned hx1 = hx0 + 1u;
            unsigned hy0 = (unsigned)i1 * PRIME_Y;
            unsigned hy1 = hy0 + PRIME_Y;
            unsigned hz0 = (unsigned)i2 * PRIME_Z;
            unsigned hz1 = hz0 + PRIME_Z;
#pragma unroll
            for (int c = 0; c < 8; ++c) {
                unsigned h = ((c & 1) ? hx1 : hx0) ^
                             (((c >> 1) & 1) ? hy1 : hy0) ^
                             (((c >> 2) & 1) ? hz1 : hz0);
                idx[c] = h & HASH_MASK;
            }
        }

        float2 v[8];
#pragma unroll
        for (int c = 0; c < 8; ++c)
            v[c] = __ldg(&table[off + (int)idx[c]]);

        const float w0a = 1.0f - f0, w1a = 1.0f - f1, w2a = 1.0f - f2;
        float ax = 0.0f, ay = 0.0f;
#pragma unroll
        for (int c = 0; c < 8; ++c) {
            float w = ((c & 1) ? f0 : w0a) * (((c >> 1) & 1) ? f1 : w1a);
            w *= (((c >> 2) & 1) ? f2 : w2a);
            ax = fmaf(w, v[c].x, ax);
            ay = fmaf(w, v[c].y, ay);
        }
        r[2 * l]     = ax;
        r[2 * l + 1] = ay;
    }

    float4* o = (float4*)(out + (size_t)b * 32);
#pragma unroll
    for (int i = 0; i < 8; ++i)
        o[i] = make_float4(r[4 * i], r[4 * i + 1], r[4 * i + 2], r[4 * i + 3]);
}

extern "C" void kernel_launch(void* const* d_in, const int* in_sizes, int n_in,
                              void* d_out, int out_size) {
    const float*  inputs = (const float*) d_in[0];
    const float2* emb    = (const float2*)d_in[1];
    const float2* fs     = (const float2*)d_in[2];
    const int*    sidx   = (const int*)   d_in[3];
    const int*    bound  = (n_in >= 5) ? (const int*)d_in[4] : nullptr;

    int npts = in_sizes[3];
    int B    = in_sizes[0] / 3;

    zero_kernel<<<1184, 256>>>();
    scatter_kernel<<<(npts + 255) / 256, 256>>>(emb, sidx, npts);
    finalize_kernel<<<(TOTAL_PARAMS + 255) / 256, 256>>>(fs, TOTAL_PARAMS);
    encode_kernel<<<(B + 255) / 256, 256>>>(inputs, bound, (float*)d_out, B);
}